// round 1
// baseline (speedup 1.0000x reference)
#include <cuda_runtime.h>
#include <math.h>

#define BATCH 32
#define NMEM 512
#define NW 8
#define QL 32
#define NC 8
#define CL 8
#define VOCAB 50000
#define EM 256
#define D 768
#define NVEC 9          // vec 0 = question, vec 1..8 = answer choices
#define HOPS 2
#define MCH 4           // m-chunks in the o-accumulation kernel

// ---------------- device scratch (static: no allocations allowed) ----------
__device__ float g_E[3 * BATCH * NMEM * D];        // 151MB: embeddings per table
__device__ float g_ua[NVEC * BATCH * D];           // rows: r = v*32+b  (u then a)
__device__ float g_vec[NVEC * BATCH * D];          // Uu / Va
__device__ float g_sc[NVEC * BATCH * NMEM];        // scores, then p in place
__device__ float g_op[MCH * NVEC * BATCH * D];     // partial o sums
__device__ float g_o[NVEC * BATCH * D];            // o_q (v=0), o_a (v=1..8)
__device__ float g_qw[BATCH * D];                  // o_q^T W

// ---------------- kernels ---------------------------------------------------

// E[t][b][m][0:256]=sum_w A_t[subj], [256:512]=rel, [512:768]=obj
__global__ void k_embed(const int* __restrict__ subj, const int* __restrict__ rel,
                        const int* __restrict__ obj, const float* __restrict__ A) {
    int m = blockIdx.x, b = blockIdx.y, t = blockIdx.z;
    int d = threadIdx.x;                       // 0..255
    const float* tab = A + (size_t)t * VOCAB * EM;
    int base = (b * NMEM + m) * NW;
    float s = 0.f, r = 0.f, o = 0.f;
#pragma unroll
    for (int w = 0; w < NW; w++) {
        int is = __ldg(subj + base + w);
        int ir = __ldg(rel + base + w);
        int io = __ldg(obj + base + w);
        s += __ldg(tab + (size_t)is * EM + d);
        r += __ldg(tab + (size_t)ir * EM + d);
        o += __ldg(tab + (size_t)io * EM + d);
    }
    float* e = g_E + ((size_t)(t * BATCH + b) * NMEM + m) * D;
    e[d] = s; e[EM + d] = r; e[2 * EM + d] = o;
}

// u[b] = sum_q B[ques];  a[c][b] = sum_w B[answerChoices]
__global__ void k_init_ua(const int* __restrict__ ques, const int* __restrict__ ac,
                          const float* __restrict__ Bt) {
    int v = blockIdx.x;            // 0..31 = u rows, 32..287 = a rows (r = 32+c*32+b)
    int d = threadIdx.x;           // 768 threads
    float acc = 0.f;
    if (v < BATCH) {
        int b = v;
        for (int q = 0; q < QL; q++)
            acc += __ldg(Bt + (size_t)__ldg(ques + b * QL + q) * D + d);
    } else {
        int idx = v - BATCH;
        int c = idx >> 5, b = idx & 31;
        for (int w = 0; w < CL; w++)
            acc += __ldg(Bt + (size_t)__ldg(ac + (b * NC + c) * CL + w) * D + d);
    }
    g_ua[(size_t)v * D + d] = acc;
}

// g_vec[r][d] = sum_e X[r][e] * M[d][e]   (M = U for row-tile 0, V otherwise)
__global__ void k_matvec(const float* __restrict__ U, const float* __restrict__ V) {
    __shared__ float sX[32][33];
    __shared__ float sM[32][33];
    int rt = blockIdx.y;           // 0..8
    int dt = blockIdx.x;           // 0..23
    const float* M = (rt == 0) ? U : V;
    int tx = threadIdx.x & 31, ty = threadIdx.x >> 5;   // 32 x 8
    float acc[4] = {0.f, 0.f, 0.f, 0.f};
    for (int e0 = 0; e0 < D; e0 += 32) {
#pragma unroll
        for (int i = 0; i < 4; i++) {
            int row = ty * 4 + i;
            sX[row][tx] = g_ua[(size_t)(rt * 32 + row) * D + e0 + tx];
            sM[row][tx] = M[(size_t)(dt * 32 + row) * D + e0 + tx];
        }
        __syncthreads();
#pragma unroll
        for (int e = 0; e < 32; e++) {
            float mv = sM[tx][e];
#pragma unroll
            for (int i = 0; i < 4; i++) acc[i] += sX[ty * 4 + i][e] * mv;
        }
        __syncthreads();
    }
#pragma unroll
    for (int i = 0; i < 4; i++)
        g_vec[(size_t)(rt * 32 + ty * 4 + i) * D + dt * 32 + tx] = acc[i];
}

// scores[v][b][m] = E[hop][b][m][:] . g_vec[v*32+b][:]
__global__ void k_scores(int hop) {
    __shared__ float sv[NVEC * D];   // 27 KB
    int b = blockIdx.y;
    int mbase = blockIdx.x * 8;
    for (int i = threadIdx.x; i < NVEC * D; i += 256) {
        int v = i / D, d = i - v * D;
        sv[i] = g_vec[(size_t)(v * BATCH + b) * D + d];
    }
    __syncthreads();
    int warp = threadIdx.x >> 5, lane = threadIdx.x & 31;
    int m = mbase + warp;
    const float* e = g_E + ((size_t)(hop * BATCH + b) * NMEM + m) * D;
    float acc[NVEC];
#pragma unroll
    for (int v = 0; v < NVEC; v++) acc[v] = 0.f;
    for (int d = lane; d < D; d += 32) {
        float ev = e[d];
#pragma unroll
        for (int v = 0; v < NVEC; v++) acc[v] += ev * sv[v * D + d];
    }
#pragma unroll
    for (int v = 0; v < NVEC; v++) {
#pragma unroll
        for (int off = 16; off; off >>= 1)
            acc[v] += __shfl_down_sync(0xffffffffu, acc[v], off);
    }
    if (lane == 0) {
#pragma unroll
        for (int v = 0; v < NVEC; v++)
            g_sc[(size_t)(v * BATCH + b) * NMEM + m] = acc[v];
    }
}

// block reduce over 512 threads: mode 0 sum, 1 max, 2 min; result broadcast
__device__ __forceinline__ float blockReduce512(float v, int mode, float* sh) {
    int t = threadIdx.x;
    sh[t] = v;
    __syncthreads();
    for (int s = 256; s > 0; s >>= 1) {
        if (t < s) {
            float a = sh[t], b = sh[t + s];
            sh[t] = (mode == 0) ? (a + b) : ((mode == 1) ? fmaxf(a, b) : fminf(a, b));
        }
        __syncthreads();
    }
    float r = sh[0];
    __syncthreads();
    return r;
}

// p = log_softmax(s); p -= min(p); p /= sum(|p + 1e-8|)
__global__ void k_renorm_q() {
    __shared__ float sh[NMEM];
    int b = blockIdx.x, m = threadIdx.x;
    size_t base = (size_t)b * NMEM;
    float s = g_sc[base + m];
    float mx = blockReduce512(s, 1, sh);
    float se = blockReduce512(expf(s - mx), 0, sh);
    float p = s - mx - logf(se);
    float mn = blockReduce512(p, 2, sh);
    p -= mn;
    float nrm = blockReduce512(fabsf(p + 1e-8f), 0, sh);
    g_sc[base + m] = p / nrm;
}

// p = log_softmax(s); norm=sum|p|; if norm==0 p+=1; norm=sum|p|; p/=norm
__global__ void k_renorm_a() {
    __shared__ float sh[NMEM];
    int c = blockIdx.x, b = blockIdx.y, m = threadIdx.x;
    size_t base = (size_t)((1 + c) * BATCH + b) * NMEM;
    float s = g_sc[base + m];
    float mx = blockReduce512(s, 1, sh);
    float se = blockReduce512(expf(s - mx), 0, sh);
    float p = s - mx - logf(se);
    float nrm = blockReduce512(fabsf(p), 0, sh);
    float p2 = (nrm == 0.f) ? (p + 1.f) : p;
    float nrm2 = blockReduce512(fabsf(p2), 0, sh);
    g_sc[base + m] = p2 / nrm2;
}

// partial o sums: g_op[mc][v][b][d] = sum_{m in chunk} p[v][b][m] * E[hop+1][b][m][d]
__global__ void k_oacc(int hop) {
    __shared__ float sp[NVEC * 128];
    int b = blockIdx.x, dc = blockIdx.y, mc = blockIdx.z;
    for (int i = threadIdx.x; i < NVEC * 128; i += 256) {
        int v = i >> 7, ml = i & 127;
        sp[i] = g_sc[(size_t)(v * BATCH + b) * NMEM + mc * 128 + ml];
    }
    __syncthreads();
    int d = dc * 256 + threadIdx.x;
    const float* e = g_E + ((size_t)((hop + 1) * BATCH + b) * NMEM + mc * 128) * D + d;
    float acc[NVEC];
#pragma unroll
    for (int v = 0; v < NVEC; v++) acc[v] = 0.f;
    for (int ml = 0; ml < 128; ml++) {
        float ev = e[(size_t)ml * D];
#pragma unroll
        for (int v = 0; v < NVEC; v++) acc[v] += ev * sp[v * 128 + ml];
    }
#pragma unroll
    for (int v = 0; v < NVEC; v++)
        g_op[(size_t)((mc * NVEC + v) * BATCH + b) * D + d] = acc[v];
}

// o = sum of 4 partials; u/a += o
__global__ void k_update() {
    const int S = NVEC * BATCH * D;
    int i = blockIdx.x * 256 + threadIdx.x;
    if (i >= S) return;
    float o = g_op[i] + g_op[i + S] + g_op[i + 2 * S] + g_op[i + 3 * S];
    g_o[i] = o;
    g_ua[i] += o;
}

// qW[b][e] = sum_d o_q[b][d] * W[d][e]
__global__ void k_qw(const float* __restrict__ W) {
    __shared__ float sq[D];
    int b = blockIdx.x, e = threadIdx.x;   // 768 threads
    sq[e] = g_o[(size_t)b * D + e];
    __syncthreads();
    float a0 = 0.f, a1 = 0.f, a2 = 0.f, a3 = 0.f;
    for (int dd = 0; dd < D; dd += 4) {
        a0 += sq[dd + 0] * __ldg(W + (size_t)(dd + 0) * D + e);
        a1 += sq[dd + 1] * __ldg(W + (size_t)(dd + 1) * D + e);
        a2 += sq[dd + 2] * __ldg(W + (size_t)(dd + 2) * D + e);
        a3 += sq[dd + 3] * __ldg(W + (size_t)(dd + 3) * D + e);
    }
    g_qw[(size_t)b * D + e] = (a0 + a1) + (a2 + a3);
}

// pred[b][c] = qW[b] . o_a[c][b]
__global__ void k_pred(float* __restrict__ out) {
    __shared__ float sh[256];
    int b = blockIdx.x, c = blockIdx.y;
    int t = threadIdx.x;
    const float* q = g_qw + (size_t)b * D;
    const float* oa = g_o + (size_t)((1 + c) * BATCH + b) * D;
    float acc = 0.f;
    for (int e = t; e < D; e += 256) acc += q[e] * oa[e];
    sh[t] = acc;
    __syncthreads();
    for (int s = 128; s > 0; s >>= 1) {
        if (t < s) sh[t] += sh[t + s];
        __syncthreads();
    }
    if (t == 0) out[b * NC + c] = sh[0];
}

// ---------------- launch ----------------------------------------------------
extern "C" void kernel_launch(void* const* d_in, const int* in_sizes, int n_in,
                              void* d_out, int out_size) {
    const int*   subj = (const int*)d_in[0];
    const int*   rel  = (const int*)d_in[1];
    const int*   obj  = (const int*)d_in[2];
    const int*   ques = (const int*)d_in[3];
    const int*   ac   = (const int*)d_in[4];
    const float* A    = (const float*)d_in[5];
    const float* Bt   = (const float*)d_in[6];
    const float* U    = (const float*)d_in[7];
    const float* V    = (const float*)d_in[8];
    const float* W    = (const float*)d_in[9];
    float* out = (float*)d_out;

    k_embed<<<dim3(NMEM, BATCH, 3), EM>>>(subj, rel, obj, A);
    k_init_ua<<<BATCH + NC * BATCH, D>>>(ques, ac, Bt);

    for (int hop = 0; hop < HOPS; hop++) {
        k_matvec<<<dim3(24, 9), 256>>>(U, V);
        k_scores<<<dim3(NMEM / 8, BATCH), 256>>>(hop);
        k_renorm_q<<<BATCH, NMEM>>>();
        k_renorm_a<<<dim3(NC, BATCH), NMEM>>>();
        k_oacc<<<dim3(BATCH, 3, MCH), 256>>>(hop);
        k_update<<<(NVEC * BATCH * D + 255) / 256, 256>>>();
    }

    k_qw<<<BATCH, D>>>(W);
    k_pred<<<dim3(BATCH, NC), 256>>>(out);
}